// round 16
// baseline (speedup 1.0000x reference)
#include <cuda_runtime.h>
#include <cuda_fp16.h>
#include <cstdint>

#define BATCH 2
#define SEQ   1024
#define HID   4096
#define NH    32
#define NKV   8
#define HD    128
#define NREP  4
#define QKV_N (NH * HD + 2 * NKV * HD)   // 6144
#define KDIM  4096
#define KC    (KDIM / 64)                // 64 k-chunks of 64

// ---------------- scratch (device globals; no allocation allowed) ----------------
__device__ __half g_hsh  [BATCH * SEQ * HID];        // hs fp16 [2048][4096]
__device__ __half g_wh   [KDIM * QKV_N];             // [Wq|Wk|Wv] fp16 [4096][6144]
__device__ __half g_woh  [KDIM * HID];               // Wo fp16 [4096][4096]
__device__ __half g_qkvh [BATCH * SEQ * QKV_N];      // fp16 row-major: q|k|v
__device__ __half g_vt   [BATCH * NKV * HD * SEQ];   // V^T: [b][kh][d][s]
__device__ __half g_attnh[BATCH * SEQ * NH * HD];    // attn fp16 [2048][4096]

// ---------------- helpers ----------------
__device__ __forceinline__ uint32_t fp2h2(float lo, float hi) {
    __half2 h = __floats2half2_rn(lo, hi);
    return *reinterpret_cast<uint32_t*>(&h);
}
__device__ __forceinline__ uint32_t smem_u32(const void* p) {
    uint32_t a;
    asm("{ .reg .u64 t; cvta.to.shared.u64 t, %1; cvt.u32.u64 %0, t; }" : "=r"(a) : "l"(p));
    return a;
}
__device__ __forceinline__ void cp16(uint32_t dst, const void* src) {
    asm volatile("cp.async.cg.shared.global [%0], [%1], 16;" :: "r"(dst), "l"(src));
}
#define CP_COMMIT() asm volatile("cp.async.commit_group;" ::: "memory")
#define CP_WAIT(n)  asm volatile("cp.async.wait_group %0;" :: "n"(n) : "memory")

__device__ __forceinline__ void ldsm4(uint32_t* r, uint32_t a) {
    asm volatile("ldmatrix.sync.aligned.m8n8.x4.shared.b16 {%0,%1,%2,%3}, [%4];"
        : "=r"(r[0]), "=r"(r[1]), "=r"(r[2]), "=r"(r[3]) : "r"(a));
}
__device__ __forceinline__ void ldsm4t(uint32_t* r, uint32_t a) {
    asm volatile("ldmatrix.sync.aligned.m8n8.x4.trans.shared.b16 {%0,%1,%2,%3}, [%4];"
        : "=r"(r[0]), "=r"(r[1]), "=r"(r[2]), "=r"(r[3]) : "r"(a));
}

// fp16 mma m16n8k16, fp32 accum
__device__ __forceinline__ void mma16h(float* d, const uint32_t* a, const uint32_t* b) {
    asm volatile(
        "mma.sync.aligned.m16n8k16.row.col.f32.f16.f16.f32 "
        "{%0,%1,%2,%3}, {%4,%5,%6,%7}, {%8,%9}, {%0,%1,%2,%3};\n"
        : "+f"(d[0]), "+f"(d[1]), "+f"(d[2]), "+f"(d[3])
        : "r"(a[0]), "r"(a[1]), "r"(a[2]), "r"(a[3]), "r"(b[0]), "r"(b[1]));
}

// ---------------- prep: pure streaming fp32 -> fp16 conversion -------------------
#define HS_E (BATCH * SEQ * HID)        // 8388608
#define W_E  (KDIM * QKV_N)             // 25165824
#define WO_E (KDIM * HID)               // 16777216
#define CVT_BLOCKS ((HS_E + W_E + WO_E) / 8 / 256)   // 24576

__global__ __launch_bounds__(256)
void cvt_all(const float* __restrict__ hs,
             const float* __restrict__ Wq, const float* __restrict__ Wk,
             const float* __restrict__ Wv, const float* __restrict__ Wo)
{
    size_t i8 = ((size_t)blockIdx.x * 256 + threadIdx.x) * 8;
    const float* src;
    __half* dst;
    if (i8 < HS_E) {
        src = hs + i8;
        dst = g_hsh + i8;
    } else if (i8 < (size_t)HS_E + W_E) {
        size_t off = i8 - HS_E;
        int k = (int)(off / QKV_N), c = (int)(off % QKV_N);
        if (c < NH * HD)                 src = Wq + (size_t)k * (NH * HD) + c;
        else if (c < NH * HD + NKV * HD) src = Wk + (size_t)k * (NKV * HD) + (c - NH * HD);
        else                             src = Wv + (size_t)k * (NKV * HD) + (c - NH * HD - NKV * HD);
        dst = g_wh + off;
    } else {
        size_t off = i8 - HS_E - W_E;
        src = Wo + off;
        dst = g_woh + off;
    }
    float4 a = *reinterpret_cast<const float4*>(src);
    float4 b = *reinterpret_cast<const float4*>(src + 4);
    uint4 o;
    o.x = fp2h2(a.x, a.y); o.y = fp2h2(a.z, a.w);
    o.z = fp2h2(b.x, b.y); o.w = fp2h2(b.z, b.w);
    *reinterpret_cast<uint4*>(dst) = o;
}

// ---------------- fp16 GEMM: block 128x128, warp 64x32, 3 stages, 2 CTA/SM -------
#define STG_B 32768                     // A 16KB + B 16KB per stage
#define NSTAGE 3
#define GEMM_SMEM (NSTAGE * STG_B)      // 98304 B

__global__ __launch_bounds__(256, 2)
void gemm_h(const __half* __restrict__ Ap, const __half* __restrict__ Bp,
            void* __restrict__ Cv, int ldb, int ldc, int half_out)
{
    extern __shared__ char smc[];
    const uint32_t sb = smem_u32(smc);
    const int tid  = threadIdx.x;
    const int lane = tid & 31, warp = tid >> 5;
    const int wm = warp >> 2, wn = warp & 3;   // 2(m) x 4(n), warp tile 64x32
    const int g = lane >> 2, t = lane & 3;
    const int m0 = blockIdx.y * 128, n0 = blockIdx.x * 128;

    float acc[4][4][4];
#pragma unroll
    for (int i = 0; i < 4; i++)
#pragma unroll
        for (int j = 0; j < 4; j++)
#pragma unroll
            for (int r = 0; r < 4; r++) acc[i][j][r] = 0.f;

    auto loadChunk = [&](int st, int kt) {
        uint32_t As = sb + st * STG_B;
        uint32_t Bs = As + 16384;
        const __half* Ag = Ap + (size_t)m0 * KDIM + kt * 64;
#pragma unroll
        for (int i = 0; i < 4; i++) {               // A: 128 rows x 8 units
            int l = i * 256 + tid;
            int r = l >> 3, u = l & 7;
            cp16(As + r * 128 + ((u ^ (r & 7)) << 4), Ag + (size_t)r * KDIM + u * 8);
        }
        const __half* Bg = Bp + (size_t)(kt * 64) * ldb + n0;
#pragma unroll
        for (int i = 0; i < 4; i++) {               // B: 64 rows x 16 units
            int l = i * 256 + tid;
            int r = l >> 4, u = l & 15;
            cp16(Bs + r * 256 + ((u ^ (r & 7)) << 4), Bg + (size_t)r * ldb + u * 8);
        }
    };

    // per-lane ldmatrix constants
    const int jA  = lane >> 3;
    const int rAl = (lane & 7) + (jA & 1) * 8;
    const int uhA = jA >> 1;
    const int e7a = rAl & 7;
    uint32_t aoff[4];
#pragma unroll
    for (int mi = 0; mi < 4; mi++) aoff[mi] = (uint32_t)(wm * 64 + mi * 16 + rAl) * 128;
    const int kbB = (lane & 7) + ((lane >> 3) & 1) * 8;
    const uint32_t bro = (uint32_t)kbB * 256;
    const int e7b = lane & 7;
    const int nhB = (lane >> 4) & 1;
    uint32_t ub[2];
#pragma unroll
    for (int nip = 0; nip < 2; nip++)
        ub[nip] = (uint32_t)(((wn * 4 + nip * 2 + nhB) ^ e7b) << 4);

    loadChunk(0, 0); CP_COMMIT();
    loadChunk(1, 1); CP_COMMIT();

    for (int c = 0; c < KC; c++) {
        CP_WAIT(1);
        __syncthreads();
        if (c + 2 < KC) loadChunk((c + 2) % NSTAGE, c + 2);
        CP_COMMIT();

        const uint32_t As = sb + (c % NSTAGE) * STG_B;
        const uint32_t Bs = As + 16384;
#pragma unroll
        for (int ks = 0; ks < 4; ks++) {
            const uint32_t axor = (uint32_t)(((2 * ks + uhA) ^ e7a) << 4);
            uint32_t af[4][4];
#pragma unroll
            for (int mi = 0; mi < 4; mi++)
                ldsm4(af[mi], As + aoff[mi] + axor);
            uint32_t bf[4][2];
#pragma unroll
            for (int nip = 0; nip < 2; nip++) {
                uint32_t r4[4];
                ldsm4t(r4, Bs + (uint32_t)(ks * 4096) + bro + ub[nip]);
                bf[2 * nip][0]     = r4[0]; bf[2 * nip][1]     = r4[1];
                bf[2 * nip + 1][0] = r4[2]; bf[2 * nip + 1][1] = r4[3];
            }
#pragma unroll
            for (int mi = 0; mi < 4; mi++)
#pragma unroll
                for (int ni = 0; ni < 4; ni++)
                    mma16h(acc[mi][ni], af[mi], bf[ni]);
        }
    }

    if (half_out) {
        __half* C = (__half*)Cv;
#pragma unroll
        for (int mi = 0; mi < 4; mi++) {
            int row = m0 + wm * 64 + mi * 16 + g;
#pragma unroll
            for (int ni = 0; ni < 4; ni++) {
                int col = n0 + wn * 32 + ni * 8 + t * 2;
                *reinterpret_cast<uint32_t*>(&C[(size_t)row * ldc + col]) =
                    fp2h2(acc[mi][ni][0], acc[mi][ni][1]);
                *reinterpret_cast<uint32_t*>(&C[(size_t)(row + 8) * ldc + col]) =
                    fp2h2(acc[mi][ni][2], acc[mi][ni][3]);
            }
        }
    } else {
        float* C = (float*)Cv;
#pragma unroll
        for (int mi = 0; mi < 4; mi++) {
            int row = m0 + wm * 64 + mi * 16 + g;
#pragma unroll
            for (int ni = 0; ni < 4; ni++) {
                int col = n0 + wn * 32 + ni * 8 + t * 2;
                *reinterpret_cast<float2*>(&C[(size_t)row * ldc + col]) =
                    make_float2(acc[mi][ni][0], acc[mi][ni][1]);
                *reinterpret_cast<float2*>(&C[(size_t)(row + 8) * ldc + col]) =
                    make_float2(acc[mi][ni][2], acc[mi][ni][3]);
            }
        }
    }
}

// ---------------- fused RoPE (vectorized) + V transpose --------------------------
// q heads folded by (1/sqrt(d)) * log2(e) so flash can use exp2f directly.
#define ROPE_BLOCKS (BATCH * SEQ * (NH + NKV) * 32 / 256)   // 10240
__global__ __launch_bounds__(256)
void rope_vt(const float* __restrict__ cosb, const float* __restrict__ sinb)
{
    __shared__ __half ts[64][72];
    if (blockIdx.x < ROPE_BLOCKS) {
        int i = blockIdx.x * 256 + threadIdx.x;
        int dh2 = i & 31;
        int h  = (i >> 5) % (NH + NKV);
        int bs = (i >> 5) / (NH + NKV);
        uint32_t* p = reinterpret_cast<uint32_t*>(g_qkvh + (size_t)bs * QKV_N + h * HD) + dh2;
        float2 x1 = __half22float2(*reinterpret_cast<__half2*>(&p[0]));
        float2 x2 = __half22float2(*reinterpret_cast<__half2*>(&p[32]));
        const float2* cb = reinterpret_cast<const float2*>(cosb + (size_t)bs * HD);
        const float2* sb = reinterpret_cast<const float2*>(sinb + (size_t)bs * HD);
        float2 c0 = cb[dh2], c1 = cb[dh2 + 32];
        float2 s0 = sb[dh2], s1 = sb[dh2 + 32];
        const float sc = (h < NH) ? 0.08838834764831845f * 1.44269504088896f : 1.0f;
        p[0]  = fp2h2((x1.x * c0.x - x2.x * s0.x) * sc, (x1.y * c0.y - x2.y * s0.y) * sc);
        p[32] = fp2h2((x2.x * c1.x + x1.x * s1.x) * sc, (x2.y * c1.y + x1.y * s1.y) * sc);
    } else {
        int idx = blockIdx.x - ROPE_BLOCKS;      // 0..511
        const int tid = threadIdx.x;
        const int st = idx & 15, yy = idx >> 4;
        const int bkh = yy >> 1, dt = yy & 1;
        const int b = bkh / NKV;
        const __half* src = g_qkvh + ((size_t)(b * SEQ + st * 64)) * QKV_N
                          + NH * HD + NKV * HD + (bkh % NKV) * HD + dt * 64;
#pragma unroll
        for (int i = 0; i < 16; i++) {
            int e = i * 256 + tid;
            int si = e >> 6, di = e & 63;
            ts[si][di] = src[(size_t)si * QKV_N + di];
        }
        __syncthreads();
        __half* dst = g_vt + ((size_t)(bkh * HD + dt * 64)) * SEQ + st * 64;
#pragma unroll
        for (int i = 0; i < 16; i++) {
            int e = i * 256 + tid;
            int di = e >> 6, si = e & 63;
            dst[(size_t)di * SEQ + si] = ts[si][di];
        }
    }
}

// ---------------- flash attention: FBQ=64, FBK=128, 128 thr, ldmatrix ------------
#define FBQ 64
#define FBK 128
#define QSH 136
#define VSH 136
#define FLASH_SMEM ((64 * QSH + 128 * 128 + 128 * VSH) * 2)   // 84992 B

__global__ __launch_bounds__(128, 3)     // reg cap ~168; occupancy smem-limited to 2
void flash_kernel()
{
    extern __shared__ __half smh[];
    __half* Qs = smh;                   // [64][QSH]
    __half* Ks = Qs + 64 * QSH;         // [128][128], unit-swizzled
    __half* Vs = Ks + 128 * 128;        // [128][VSH]  (V^T: d rows, s inner)

    const int tid  = threadIdx.x;
    const int lane = tid & 31, warp = tid >> 5;
    const int g = lane >> 2, t = lane & 3;
    const int qt = (int)gridDim.x - 1 - (int)blockIdx.x;   // longest CTAs first
    const int h = blockIdx.y, b = blockIdx.z;
    const int q0 = qt * FBQ;
    const int kh = h / NREP;
    const int r0 = warp * 16;

    const __half* Qg  = g_qkvh + ((size_t)(b * SEQ + q0)) * QKV_N + h * HD;
    const __half* Kb  = g_qkvh + (size_t)b * SEQ * QKV_N + NH * HD + kh * HD;
    const __half* Vtb = g_vt + ((size_t)(b * NKV + kh)) * HD * SEQ;

    auto issueKV = [&](int kt) {
        const __half* Kg = Kb + (size_t)(kt * FBK) * QKV_N;
#pragma unroll
        for (int i = 0; i < 16; i++) {         // K: 128 rows x 16 swizzled units
            int l = i * 128 + tid;
            int r = l >> 4, cs = l & 15;
            cp16(smem_u32(Ks + r * 128 + ((cs ^ (r & 7)) << 3)), Kg + (size_t)r * QKV_N + cs * 8);
        }
        const __half* Vg = Vtb + kt * FBK;
#pragma unroll
        for (int i = 0; i < 16; i++) {         // V^T: 128 d-rows x 128 s-cols
            int l = i * 128 + tid;
            int r = l >> 4, c = (l & 15) << 3;
            cp16(smem_u32(Vs + r * VSH + c), Vg + (size_t)r * SEQ + c);
        }
    };

#pragma unroll
    for (int i = 0; i < 8; i++) {              // Q: 64 rows x 128 halves
        int l = i * 128 + tid;
        int r = l >> 4, c = (l & 15) << 3;
        cp16(smem_u32(Qs + r * QSH + c), Qg + (size_t)r * QKV_N + c);
    }
    issueKV(0);
    CP_COMMIT();

    // per-lane ldmatrix base addresses (immediate offsets in loops; no arrays)
    const int e7  = lane & 7;
    const int kof = (lane >> 3) & 1;
    const int nh16 = (lane >> 4) & 1;
    const uint32_t qb0 = smem_u32(Qs) + (uint32_t)(r0 + e7 + kof * 8) * (QSH * 2)
                       + (uint32_t)nh16 * 16;
    const uint32_t kbase = smem_u32(Ks) + (uint32_t)(nh16 * 8 + e7) * 256;
    const uint32_t vbase = smem_u32(Vs) + (uint32_t)(nh16 * 8 + e7) * (VSH * 2)
                         + (uint32_t)kof * 16;

    float o[16][4];
#pragma unroll
    for (int n = 0; n < 16; n++)
#pragma unroll
        for (int r = 0; r < 4; r++) o[n][r] = 0.f;
    float mrow[2] = {-1e30f, -1e30f};
    float lrow[2] = {0.f, 0.f};

    const int nkt = (qt >> 1) + 1;
    for (int kt = 0; kt < nkt; kt++) {
        CP_WAIT(0);
        __syncthreads();

        // S = Q @ K^T  (ldmatrix operand loads; Q pre-scaled by log2e/sqrt(d))
        float s[16][4];
#pragma unroll
        for (int j = 0; j < 16; j++)
#pragma unroll
            for (int r = 0; r < 4; r++) s[j][r] = 0.f;
#pragma unroll
        for (int ks = 0; ks < 8; ks++) {
            uint32_t af[4];
            ldsm4(af, qb0 + 32 * ks);
            const uint32_t kx = (uint32_t)(((2 * ks + kof) ^ e7) << 4);
#pragma unroll
            for (int i = 0; i < 8; i++) {
                uint32_t r4[4];
                ldsm4(r4, kbase + (uint32_t)(i * 4096) + kx);
                mma16h(s[2 * i],     af, r4);
                mma16h(s[2 * i + 1], af, r4 + 2);
            }
        }

        // online softmax (base-2); mask only the diagonal k-tile
        const int row_lo = q0 + r0 + g;
        float nm[2] = {mrow[0], mrow[1]};
        if (kt == (qt >> 1)) {
            const int k0 = kt * FBK;
#pragma unroll
            for (int j = 0; j < 16; j++) {
                int col = k0 + j * 8 + 2 * t;
                s[j][0] = (col     <= row_lo)     ? s[j][0] : -1e30f;
                s[j][1] = (col + 1 <= row_lo)     ? s[j][1] : -1e30f;
                s[j][2] = (col     <= row_lo + 8) ? s[j][2] : -1e30f;
                s[j][3] = (col + 1 <= row_lo + 8) ? s[j][3] : -1e30f;
            }
        }
#pragma unroll
        for (int j = 0; j < 16; j++) {
            nm[0] = fmaxf(nm[0], fmaxf(s[j][0], s[j][1]));
            nm[1] = fmaxf(nm[1], fmaxf(s[j][2], s[j][3]));
        }
#pragma unroll
        for (int dd = 1; dd < 4; dd <<= 1) {
            nm[0] = fmaxf(nm[0], __shfl_xor_sync(0xffffffffu, nm[0], dd));
            nm[1] = fmaxf(nm[1], __shfl_xor_sync(0xffffffffu, nm[1], dd));
        }
        float alpha0 = exp2f(mrow[0] - nm[0]);
        float alpha1 = exp2f(mrow[1] - nm[1]);
        mrow[0] = nm[0]; mrow[1] = nm[1];
        float rs0 = 0.f, rs1 = 0.f;
#pragma unroll
        for (int j = 0; j < 16; j++) {
            s[j][0] = exp2f(s[j][0] - nm[0]);
            s[j][1] = exp2f(s[j][1] - nm[0]);
            s[j][2] = exp2f(s[j][2] - nm[1]);
            s[j][3] = exp2f(s[j][3] - nm[1]);
            rs0 += s[j][0] + s[j][1];
            rs1 += s[j][2] + s[j][3];
        }
#pragma unroll
        for (int dd = 1; dd < 4; dd <<= 1) {
            rs0 += __shfl_xor_sync(0xffffffffu, rs0, dd);
            rs1 += __shfl_xor_sync(0xffffffffu, rs1, dd);
        }
        lrow[0] = lrow[0] * alpha0 + rs0;
        lrow[1] = lrow[1] * alpha1 + rs1;
#pragma unroll
        for (int n = 0; n < 16; n++) {
            o[n][0] *= alpha0; o[n][1] *= alpha0;
            o[n][2] *= alpha1; o[n][3] *= alpha1;
        }

        // O += P @ V  (P fp16 inline; V via ldmatrix, immediate offsets)
#pragma unroll
        for (int ks = 0; ks < 8; ks++) {
            uint32_t af[4];
            af[0] = fp2h2(s[2 * ks][0],     s[2 * ks][1]);
            af[1] = fp2h2(s[2 * ks][2],     s[2 * ks][3]);
            af[2] = fp2h2(s[2 * ks + 1][0], s[2 * ks + 1][1]);
            af[3] = fp2h2(s[2 * ks + 1][2], s[2 * ks + 1][3]);
#pragma unroll
            for (int i = 0; i < 8; i++) {
                uint32_t r4[4];
                ldsm4(r4, vbase + (uint32_t)(i * 16 * VSH * 2) + 32 * ks);
                mma16h(o[2 * i],     af, r4);
                mma16h(o[2 * i + 1], af, r4 + 2);
            }
        }

        __syncthreads();
        if (kt + 1 < nkt) issueKV(kt + 1);
        CP_COMMIT();
    }

    // normalize + write g_attnh row-major fp16 (A operand of the O-proj GEMM)
    float inv0 = 1.f / lrow[0], inv1 = 1.f / lrow[1];
    __half* Og = g_attnh + (size_t)(b * SEQ + q0 + r0 + g) * (NH * HD) + h * HD;
#pragma unroll
    for (int n = 0; n < 16; n++) {
        int col = n * 8 + 2 * t;
        *reinterpret_cast<uint32_t*>(&Og[col]) = fp2h2(o[n][0] * inv0, o[n][1] * inv0);
        *reinterpret_cast<uint32_t*>(&Og[(size_t)8 * NH * HD + col]) =
            fp2h2(o[n][2] * inv1, o[n][3] * inv1);
    }
}

// ---------------- launch ----------------
extern "C" void kernel_launch(void* const* d_in, const int* in_sizes, int n_in,
                              void* d_out, int out_size)
{
    const float* hs   = (const float*)d_in[0];
    const float* cosb = (const float*)d_in[1];
    const float* sinb = (const float*)d_in[2];
    // d_in[3] = attention_mask (pure causal; applied analytically in-kernel)
    const float* Wq = (const float*)d_in[4];
    const float* Wk = (const float*)d_in[5];
    const float* Wv = (const float*)d_in[6];
    const float* Wo = (const float*)d_in[7];
    float* out = (float*)d_out;

    __half *hshp, *whp, *wohp, *qkvh, *attnp;
    cudaGetSymbolAddress((void**)&hshp,  g_hsh);
    cudaGetSymbolAddress((void**)&whp,   g_wh);
    cudaGetSymbolAddress((void**)&wohp,  g_woh);
    cudaGetSymbolAddress((void**)&qkvh,  g_qkvh);
    cudaGetSymbolAddress((void**)&attnp, g_attnh);

    cudaFuncSetAttribute(gemm_h, cudaFuncAttributeMaxDynamicSharedMemorySize, GEMM_SMEM);
    cudaFuncSetAttribute(flash_kernel, cudaFuncAttributeMaxDynamicSharedMemorySize, FLASH_SMEM);

    const int M = BATCH * SEQ;

    // prep: pure streaming fp32->fp16
    cvt_all<<<CVT_BLOCKS, 256>>>(hs, Wq, Wk, Wv, Wo);

    // fused QKV projection -> fp16 g_qkvh
    gemm_h<<<dim3(QKV_N / 128, M / 128), 256, GEMM_SMEM>>>(hshp, whp, qkvh, QKV_N, QKV_N, 1);

    // fused vectorized RoPE (q scaled by log2e/sqrt(d)) + V^T
    rope_vt<<<ROPE_BLOCKS + 512, 256>>>(cosb, sinb);

    // flash: 64-row q tiles, 128 threads, ldmatrix operand loads
    flash_kernel<<<dim3(SEQ / FBQ, NH, BATCH), 128, FLASH_SMEM>>>();

    // output projection: out = attn @ Wo, fp32 output
    gemm_h<<<dim3(HID / 128, M / 128), 256, GEMM_SMEM>>>(attnp, wohp, out, HID, HID, 0);
}

// round 17
// speedup vs baseline: 1.0270x; 1.0270x over previous
#include <cuda_runtime.h>
#include <cuda_fp16.h>
#include <cstdint>

#define BATCH 2
#define SEQ   1024
#define HID   4096
#define NH    32
#define NKV   8
#define HD    128
#define NREP  4
#define QKV_N (NH * HD + 2 * NKV * HD)   // 6144
#define KDIM  4096
#define KC    (KDIM / 64)                // 64 k-chunks of 64

// ---------------- scratch (device globals; no allocation allowed) ----------------
__device__ __half g_hsh  [BATCH * SEQ * HID];        // hs fp16 [2048][4096]
__device__ __half g_wh   [KDIM * QKV_N];             // [Wq|Wk|Wv] fp16 [4096][6144]
__device__ __half g_woh  [KDIM * HID];               // Wo fp16 [4096][4096]
__device__ __half g_qkvh [BATCH * SEQ * QKV_N];      // fp16 row-major: q|k|v
__device__ __half g_vt   [BATCH * NKV * HD * SEQ];   // V^T: [b][kh][d][s]
__device__ __half g_attnh[BATCH * SEQ * NH * HD];    // attn fp16 [2048][4096]

// ---------------- helpers ----------------
__device__ __forceinline__ uint32_t fp2h2(float lo, float hi) {
    __half2 h = __floats2half2_rn(lo, hi);
    return *reinterpret_cast<uint32_t*>(&h);
}
__device__ __forceinline__ uint32_t smem_u32(const void* p) {
    uint32_t a;
    asm("{ .reg .u64 t; cvta.to.shared.u64 t, %1; cvt.u32.u64 %0, t; }" : "=r"(a) : "l"(p));
    return a;
}
__device__ __forceinline__ void cp16(uint32_t dst, const void* src) {
    asm volatile("cp.async.cg.shared.global [%0], [%1], 16;" :: "r"(dst), "l"(src));
}
#define CP_COMMIT() asm volatile("cp.async.commit_group;" ::: "memory")
#define CP_WAIT(n)  asm volatile("cp.async.wait_group %0;" :: "n"(n) : "memory")

__device__ __forceinline__ void ldsm4(uint32_t* r, uint32_t a) {
    asm volatile("ldmatrix.sync.aligned.m8n8.x4.shared.b16 {%0,%1,%2,%3}, [%4];"
        : "=r"(r[0]), "=r"(r[1]), "=r"(r[2]), "=r"(r[3]) : "r"(a));
}
__device__ __forceinline__ void ldsm4t(uint32_t* r, uint32_t a) {
    asm volatile("ldmatrix.sync.aligned.m8n8.x4.trans.shared.b16 {%0,%1,%2,%3}, [%4];"
        : "=r"(r[0]), "=r"(r[1]), "=r"(r[2]), "=r"(r[3]) : "r"(a));
}

// fp16 mma m16n8k16, fp32 accum
__device__ __forceinline__ void mma16h(float* d, const uint32_t* a, const uint32_t* b) {
    asm volatile(
        "mma.sync.aligned.m16n8k16.row.col.f32.f16.f16.f32 "
        "{%0,%1,%2,%3}, {%4,%5,%6,%7}, {%8,%9}, {%0,%1,%2,%3};\n"
        : "+f"(d[0]), "+f"(d[1]), "+f"(d[2]), "+f"(d[3])
        : "r"(a[0]), "r"(a[1]), "r"(a[2]), "r"(a[3]), "r"(b[0]), "r"(b[1]));
}

// ---------------- prep: pure streaming fp32 -> fp16 conversion -------------------
#define HS_E (BATCH * SEQ * HID)        // 8388608
#define W_E  (KDIM * QKV_N)             // 25165824
#define WO_E (KDIM * HID)               // 16777216
#define CVT_BLOCKS ((HS_E + W_E + WO_E) / 8 / 256)   // 24576

__global__ __launch_bounds__(256)
void cvt_all(const float* __restrict__ hs,
             const float* __restrict__ Wq, const float* __restrict__ Wk,
             const float* __restrict__ Wv, const float* __restrict__ Wo)
{
    size_t i8 = ((size_t)blockIdx.x * 256 + threadIdx.x) * 8;
    const float* src;
    __half* dst;
    if (i8 < HS_E) {
        src = hs + i8;
        dst = g_hsh + i8;
    } else if (i8 < (size_t)HS_E + W_E) {
        size_t off = i8 - HS_E;
        int k = (int)(off / QKV_N), c = (int)(off % QKV_N);
        if (c < NH * HD)                 src = Wq + (size_t)k * (NH * HD) + c;
        else if (c < NH * HD + NKV * HD) src = Wk + (size_t)k * (NKV * HD) + (c - NH * HD);
        else                             src = Wv + (size_t)k * (NKV * HD) + (c - NH * HD - NKV * HD);
        dst = g_wh + off;
    } else {
        size_t off = i8 - HS_E - W_E;
        src = Wo + off;
        dst = g_woh + off;
    }
    float4 a = *reinterpret_cast<const float4*>(src);
    float4 b = *reinterpret_cast<const float4*>(src + 4);
    uint4 o;
    o.x = fp2h2(a.x, a.y); o.y = fp2h2(a.z, a.w);
    o.z = fp2h2(b.x, b.y); o.w = fp2h2(b.z, b.w);
    *reinterpret_cast<uint4*>(dst) = o;
}

// ---------------- fp16 GEMM: block 128x128, warp 64x32, 3 stages, 2 CTA/SM -------
#define STG_B 32768                     // A 16KB + B 16KB per stage
#define NSTAGE 3
#define GEMM_SMEM (NSTAGE * STG_B)      // 98304 B

__global__ __launch_bounds__(256, 2)
void gemm_h(const __half* __restrict__ Ap, const __half* __restrict__ Bp,
            void* __restrict__ Cv, int ldb, int ldc, int half_out)
{
    extern __shared__ char smc[];
    const uint32_t sb = smem_u32(smc);
    const int tid  = threadIdx.x;
    const int lane = tid & 31, warp = tid >> 5;
    const int wm = warp >> 2, wn = warp & 3;   // 2(m) x 4(n), warp tile 64x32
    const int g = lane >> 2, t = lane & 3;
    const int m0 = blockIdx.y * 128, n0 = blockIdx.x * 128;

    float acc[4][4][4];
#pragma unroll
    for (int i = 0; i < 4; i++)
#pragma unroll
        for (int j = 0; j < 4; j++)
#pragma unroll
            for (int r = 0; r < 4; r++) acc[i][j][r] = 0.f;

    auto loadChunk = [&](int st, int kt) {
        uint32_t As = sb + st * STG_B;
        uint32_t Bs = As + 16384;
        const __half* Ag = Ap + (size_t)m0 * KDIM + kt * 64;
#pragma unroll
        for (int i = 0; i < 4; i++) {               // A: 128 rows x 8 units
            int l = i * 256 + tid;
            int r = l >> 3, u = l & 7;
            cp16(As + r * 128 + ((u ^ (r & 7)) << 4), Ag + (size_t)r * KDIM + u * 8);
        }
        const __half* Bg = Bp + (size_t)(kt * 64) * ldb + n0;
#pragma unroll
        for (int i = 0; i < 4; i++) {               // B: 64 rows x 16 units
            int l = i * 256 + tid;
            int r = l >> 4, u = l & 15;
            cp16(Bs + r * 256 + ((u ^ (r & 7)) << 4), Bg + (size_t)r * ldb + u * 8);
        }
    };

    // per-lane ldmatrix constants
    const int jA  = lane >> 3;
    const int rAl = (lane & 7) + (jA & 1) * 8;
    const int uhA = jA >> 1;
    const int e7a = rAl & 7;
    uint32_t aoff[4];
#pragma unroll
    for (int mi = 0; mi < 4; mi++) aoff[mi] = (uint32_t)(wm * 64 + mi * 16 + rAl) * 128;
    const int kbB = (lane & 7) + ((lane >> 3) & 1) * 8;
    const uint32_t bro = (uint32_t)kbB * 256;
    const int e7b = lane & 7;
    const int nhB = (lane >> 4) & 1;
    uint32_t ub[2];
#pragma unroll
    for (int nip = 0; nip < 2; nip++)
        ub[nip] = (uint32_t)(((wn * 4 + nip * 2 + nhB) ^ e7b) << 4);

    loadChunk(0, 0); CP_COMMIT();
    loadChunk(1, 1); CP_COMMIT();

    for (int c = 0; c < KC; c++) {
        CP_WAIT(1);
        __syncthreads();
        if (c + 2 < KC) loadChunk((c + 2) % NSTAGE, c + 2);
        CP_COMMIT();

        const uint32_t As = sb + (c % NSTAGE) * STG_B;
        const uint32_t Bs = As + 16384;
#pragma unroll
        for (int ks = 0; ks < 4; ks++) {
            const uint32_t axor = (uint32_t)(((2 * ks + uhA) ^ e7a) << 4);
            uint32_t af[4][4];
#pragma unroll
            for (int mi = 0; mi < 4; mi++)
                ldsm4(af[mi], As + aoff[mi] + axor);
            uint32_t bf[4][2];
#pragma unroll
            for (int nip = 0; nip < 2; nip++) {
                uint32_t r4[4];
                ldsm4t(r4, Bs + (uint32_t)(ks * 4096) + bro + ub[nip]);
                bf[2 * nip][0]     = r4[0]; bf[2 * nip][1]     = r4[1];
                bf[2 * nip + 1][0] = r4[2]; bf[2 * nip + 1][1] = r4[3];
            }
#pragma unroll
            for (int mi = 0; mi < 4; mi++)
#pragma unroll
                for (int ni = 0; ni < 4; ni++)
                    mma16h(acc[mi][ni], af[mi], bf[ni]);
        }
    }

    if (half_out) {
        __half* C = (__half*)Cv;
#pragma unroll
        for (int mi = 0; mi < 4; mi++) {
            int row = m0 + wm * 64 + mi * 16 + g;
#pragma unroll
            for (int ni = 0; ni < 4; ni++) {
                int col = n0 + wn * 32 + ni * 8 + t * 2;
                *reinterpret_cast<uint32_t*>(&C[(size_t)row * ldc + col]) =
                    fp2h2(acc[mi][ni][0], acc[mi][ni][1]);
                *reinterpret_cast<uint32_t*>(&C[(size_t)(row + 8) * ldc + col]) =
                    fp2h2(acc[mi][ni][2], acc[mi][ni][3]);
            }
        }
    } else {
        float* C = (float*)Cv;
#pragma unroll
        for (int mi = 0; mi < 4; mi++) {
            int row = m0 + wm * 64 + mi * 16 + g;
#pragma unroll
            for (int ni = 0; ni < 4; ni++) {
                int col = n0 + wn * 32 + ni * 8 + t * 2;
                *reinterpret_cast<float2*>(&C[(size_t)row * ldc + col]) =
                    make_float2(acc[mi][ni][0], acc[mi][ni][1]);
                *reinterpret_cast<float2*>(&C[(size_t)(row + 8) * ldc + col]) =
                    make_float2(acc[mi][ni][2], acc[mi][ni][3]);
            }
        }
    }
}

// ---------------- fused RoPE (vectorized) + V transpose --------------------------
// q heads folded by (1/sqrt(d)) * log2(e) so flash can use exp2f directly.
#define ROPE_BLOCKS (BATCH * SEQ * (NH + NKV) * 32 / 256)   // 10240
__global__ __launch_bounds__(256)
void rope_vt(const float* __restrict__ cosb, const float* __restrict__ sinb)
{
    __shared__ __half ts[64][72];
    if (blockIdx.x < ROPE_BLOCKS) {
        int i = blockIdx.x * 256 + threadIdx.x;
        int dh2 = i & 31;
        int h  = (i >> 5) % (NH + NKV);
        int bs = (i >> 5) / (NH + NKV);
        uint32_t* p = reinterpret_cast<uint32_t*>(g_qkvh + (size_t)bs * QKV_N + h * HD) + dh2;
        float2 x1 = __half22float2(*reinterpret_cast<__half2*>(&p[0]));
        float2 x2 = __half22float2(*reinterpret_cast<__half2*>(&p[32]));
        const float2* cb = reinterpret_cast<const float2*>(cosb + (size_t)bs * HD);
        const float2* sb = reinterpret_cast<const float2*>(sinb + (size_t)bs * HD);
        float2 c0 = cb[dh2], c1 = cb[dh2 + 32];
        float2 s0 = sb[dh2], s1 = sb[dh2 + 32];
        const float sc = (h < NH) ? 0.08838834764831845f * 1.44269504088896f : 1.0f;
        p[0]  = fp2h2((x1.x * c0.x - x2.x * s0.x) * sc, (x1.y * c0.y - x2.y * s0.y) * sc);
        p[32] = fp2h2((x2.x * c1.x + x1.x * s1.x) * sc, (x2.y * c1.y + x1.y * s1.y) * sc);
    } else {
        int idx = blockIdx.x - ROPE_BLOCKS;      // 0..511
        const int tid = threadIdx.x;
        const int st = idx & 15, yy = idx >> 4;
        const int bkh = yy >> 1, dt = yy & 1;
        const int b = bkh / NKV;
        const __half* src = g_qkvh + ((size_t)(b * SEQ + st * 64)) * QKV_N
                          + NH * HD + NKV * HD + (bkh % NKV) * HD + dt * 64;
#pragma unroll
        for (int i = 0; i < 16; i++) {
            int e = i * 256 + tid;
            int si = e >> 6, di = e & 63;
            ts[si][di] = src[(size_t)si * QKV_N + di];
        }
        __syncthreads();
        __half* dst = g_vt + ((size_t)(bkh * HD + dt * 64)) * SEQ + st * 64;
#pragma unroll
        for (int i = 0; i < 16; i++) {
            int e = i * 256 + tid;
            int di = e >> 6, si = e & 63;
            dst[(size_t)di * SEQ + si] = ts[si][di];
        }
    }
}

// ---------------- flash attention: FBQ=64, FBK=128, 128 thr, split prefetch ------
#define FBQ 64
#define FBK 128
#define QSH 136
#define VSH 136
#define FLASH_SMEM ((64 * QSH + 128 * 128 + 128 * VSH) * 2)   // 84992 B

__global__ __launch_bounds__(128)        // no reg cap (255 = legit scheduling slack)
void flash_kernel()
{
    extern __shared__ __half smh[];
    __half* Qs = smh;                   // [64][QSH]
    __half* Ks = Qs + 64 * QSH;         // [128][128], unit-swizzled
    __half* Vs = Ks + 128 * 128;        // [128][VSH]  (V^T: d rows, s inner)

    const int tid  = threadIdx.x;
    const int lane = tid & 31, warp = tid >> 5;
    const int g = lane >> 2, t = lane & 3;
    const int qt = (int)gridDim.x - 1 - (int)blockIdx.x;   // longest CTAs first
    const int h = blockIdx.y, b = blockIdx.z;
    const int q0 = qt * FBQ;
    const int kh = h / NREP;
    const int r0 = warp * 16;

    const __half* Qg  = g_qkvh + ((size_t)(b * SEQ + q0)) * QKV_N + h * HD;
    const __half* Kb  = g_qkvh + (size_t)b * SEQ * QKV_N + NH * HD + kh * HD;
    const __half* Vtb = g_vt + ((size_t)(b * NKV + kh)) * HD * SEQ;

    auto issueK = [&](int kt) {
        const __half* Kg = Kb + (size_t)(kt * FBK) * QKV_N;
#pragma unroll
        for (int i = 0; i < 16; i++) {         // K: 128 rows x 16 swizzled units
            int l = i * 128 + tid;
            int r = l >> 4, cs = l & 15;
            cp16(smem_u32(Ks + r * 128 + ((cs ^ (r & 7)) << 3)), Kg + (size_t)r * QKV_N + cs * 8);
        }
    };
    auto issueV = [&](int kt) {
        const __half* Vg = Vtb + kt * FBK;
#pragma unroll
        for (int i = 0; i < 16; i++) {         // V^T: 128 d-rows x 128 s-cols
            int l = i * 128 + tid;
            int r = l >> 4, c = (l & 15) << 3;
            cp16(smem_u32(Vs + r * VSH + c), Vg + (size_t)r * SEQ + c);
        }
    };

#pragma unroll
    for (int i = 0; i < 8; i++) {              // Q: 64 rows x 128 halves
        int l = i * 128 + tid;
        int r = l >> 4, c = (l & 15) << 3;
        cp16(smem_u32(Qs + r * QSH + c), Qg + (size_t)r * QKV_N + c);
    }
    issueK(0);
    issueV(0);
    CP_COMMIT();

    // per-lane ldmatrix base addresses
    const int e7  = lane & 7;
    const int kof = (lane >> 3) & 1;
    const int nh16 = (lane >> 4) & 1;
    const uint32_t qb0 = smem_u32(Qs) + (uint32_t)(r0 + e7 + kof * 8) * (QSH * 2)
                       + (uint32_t)nh16 * 16;
    const uint32_t kbase = smem_u32(Ks) + (uint32_t)(nh16 * 8 + e7) * 256;
    const uint32_t vbase = smem_u32(Vs) + (uint32_t)(nh16 * 8 + e7) * (VSH * 2)
                         + (uint32_t)kof * 16;

    float o[16][4];
#pragma unroll
    for (int n = 0; n < 16; n++)
#pragma unroll
        for (int r = 0; r < 4; r++) o[n][r] = 0.f;
    float mrow[2] = {-1e30f, -1e30f};
    float lrow[2] = {0.f, 0.f};

    const int nkt = (qt >> 1) + 1;
    for (int kt = 0; kt < nkt; kt++) {
        const bool more = (kt + 1 < nkt);
        CP_WAIT(0);
        __syncthreads();    // K(kt), V(kt) resident

        // S = Q @ K^T  (ldmatrix operand loads; Q pre-scaled by log2e/sqrt(d))
        float s[16][4];
#pragma unroll
        for (int j = 0; j < 16; j++)
#pragma unroll
            for (int r = 0; r < 4; r++) s[j][r] = 0.f;
#pragma unroll
        for (int ks = 0; ks < 8; ks++) {
            uint32_t af[4];
            ldsm4(af, qb0 + 32 * ks);
            const uint32_t kx = (uint32_t)(((2 * ks + kof) ^ e7) << 4);
#pragma unroll
            for (int i = 0; i < 8; i++) {
                uint32_t r4[4];
                ldsm4(r4, kbase + (uint32_t)(i * 4096) + kx);
                mma16h(s[2 * i],     af, r4);
                mma16h(s[2 * i + 1], af, r4 + 2);
            }
        }

        // Ks is dead now — prefetch K(kt+1) so its load overlaps softmax + P@V
        __syncthreads();    // all warps done reading Ks
        if (more) { issueK(kt + 1); CP_COMMIT(); }

        // online softmax (base-2); mask only the diagonal k-tile
        const int row_lo = q0 + r0 + g;
        float nm[2] = {mrow[0], mrow[1]};
        if (kt == (qt >> 1)) {
            const int k0 = kt * FBK;
#pragma unroll
            for (int j = 0; j < 16; j++) {
                int col = k0 + j * 8 + 2 * t;
                s[j][0] = (col     <= row_lo)     ? s[j][0] : -1e30f;
                s[j][1] = (col + 1 <= row_lo)     ? s[j][1] : -1e30f;
                s[j][2] = (col     <= row_lo + 8) ? s[j][2] : -1e30f;
                s[j][3] = (col + 1 <= row_lo + 8) ? s[j][3] : -1e30f;
            }
        }
#pragma unroll
        for (int j = 0; j < 16; j++) {
            nm[0] = fmaxf(nm[0], fmaxf(s[j][0], s[j][1]));
            nm[1] = fmaxf(nm[1], fmaxf(s[j][2], s[j][3]));
        }
#pragma unroll
        for (int dd = 1; dd < 4; dd <<= 1) {
            nm[0] = fmaxf(nm[0], __shfl_xor_sync(0xffffffffu, nm[0], dd));
            nm[1] = fmaxf(nm[1], __shfl_xor_sync(0xffffffffu, nm[1], dd));
        }
        float alpha0 = exp2f(mrow[0] - nm[0]);
        float alpha1 = exp2f(mrow[1] - nm[1]);
        mrow[0] = nm[0]; mrow[1] = nm[1];
        float rs0 = 0.f, rs1 = 0.f;
#pragma unroll
        for (int j = 0; j < 16; j++) {
            s[j][0] = exp2f(s[j][0] - nm[0]);
            s[j][1] = exp2f(s[j][1] - nm[0]);
            s[j][2] = exp2f(s[j][2] - nm[1]);
            s[j][3] = exp2f(s[j][3] - nm[1]);
            rs0 += s[j][0] + s[j][1];
            rs1 += s[j][2] + s[j][3];
        }
#pragma unroll
        for (int dd = 1; dd < 4; dd <<= 1) {
            rs0 += __shfl_xor_sync(0xffffffffu, rs0, dd);
            rs1 += __shfl_xor_sync(0xffffffffu, rs1, dd);
        }
        lrow[0] = lrow[0] * alpha0 + rs0;
        lrow[1] = lrow[1] * alpha1 + rs1;
#pragma unroll
        for (int n = 0; n < 16; n++) {
            o[n][0] *= alpha0; o[n][1] *= alpha0;
            o[n][2] *= alpha1; o[n][3] *= alpha1;
        }

        // O += P @ V  (P fp16 inline; V via ldmatrix, immediate offsets)
#pragma unroll
        for (int ks = 0; ks < 8; ks++) {
            uint32_t af[4];
            af[0] = fp2h2(s[2 * ks][0],     s[2 * ks][1]);
            af[1] = fp2h2(s[2 * ks][2],     s[2 * ks][3]);
            af[2] = fp2h2(s[2 * ks + 1][0], s[2 * ks + 1][1]);
            af[3] = fp2h2(s[2 * ks + 1][2], s[2 * ks + 1][3]);
#pragma unroll
            for (int i = 0; i < 8; i++) {
                uint32_t r4[4];
                ldsm4(r4, vbase + (uint32_t)(i * 16 * VSH * 2) + 32 * ks);
                mma16h(o[2 * i],     af, r4);
                mma16h(o[2 * i + 1], af, r4 + 2);
            }
        }

        __syncthreads();    // all warps done reading Vs
        if (more) { issueV(kt + 1); CP_COMMIT(); }
    }

    // normalize + write g_attnh row-major fp16 (A operand of the O-proj GEMM)
    float inv0 = 1.f / lrow[0], inv1 = 1.f / lrow[1];
    __half* Og = g_attnh + (size_t)(b * SEQ + q0 + r0 + g) * (NH * HD) + h * HD;
#pragma unroll
    for (int n = 0; n < 16; n++) {
        int col = n * 8 + 2 * t;
        *reinterpret_cast<uint32_t*>(&Og[col]) = fp2h2(o[n][0] * inv0, o[n][1] * inv0);
        *reinterpret_cast<uint32_t*>(&Og[(size_t)8 * NH * HD + col]) =
            fp2h2(o[n][2] * inv1, o[n][3] * inv1);
    }
}

// ---------------- launch ----------------
extern "C" void kernel_launch(void* const* d_in, const int* in_sizes, int n_in,
                              void* d_out, int out_size)
{
    const float* hs   = (const float*)d_in[0];
    const float* cosb = (const float*)d_in[1];
    const float* sinb = (const float*)d_in[2];
    // d_in[3] = attention_mask (pure causal; applied analytically in-kernel)
    const float* Wq = (const float*)d_in[4];
    const float* Wk = (const float*)d_in[5];
    const float* Wv = (const float*)d_in[6];
    const float* Wo = (const float*)d_in[7];
    float* out = (float*)d_out;

    __half *hshp, *whp, *wohp, *qkvh, *attnp;
    cudaGetSymbolAddress((void**)&hshp,  g_hsh);
    cudaGetSymbolAddress((void**)&whp,   g_wh);
    cudaGetSymbolAddress((void**)&wohp,  g_woh);
    cudaGetSymbolAddress((void**)&qkvh,  g_qkvh);
    cudaGetSymbolAddress((void**)&attnp, g_attnh);

    cudaFuncSetAttribute(gemm_h, cudaFuncAttributeMaxDynamicSharedMemorySize, GEMM_SMEM);
    cudaFuncSetAttribute(flash_kernel, cudaFuncAttributeMaxDynamicSharedMemorySize, FLASH_SMEM);

    const int M = BATCH * SEQ;

    // prep: pure streaming fp32->fp16
    cvt_all<<<CVT_BLOCKS, 256>>>(hs, Wq, Wk, Wv, Wo);

    // fused QKV projection -> fp16 g_qkvh
    gemm_h<<<dim3(QKV_N / 128, M / 128), 256, GEMM_SMEM>>>(hshp, whp, qkvh, QKV_N, QKV_N, 1);

    // fused vectorized RoPE (q scaled by log2e/sqrt(d)) + V^T
    rope_vt<<<ROPE_BLOCKS + 512, 256>>>(cosb, sinb);

    // flash: 64-row q tiles, 128 threads, split K/V prefetch
    flash_kernel<<<dim3(SEQ / FBQ, NH, BATCH), 128, FLASH_SMEM>>>();

    // output projection: out = attn @ Wo, fp32 output
    gemm_h<<<dim3(HID / 128, M / 128), 256, GEMM_SMEM>>>(attnp, wohp, out, HID, HID, 0);
}